// round 4
// baseline (speedup 1.0000x reference)
#include <cuda_runtime.h>
#include <cstdio>

// Problem constants
#define BATCH 8
#define CIN   256
#define COUT  256
#define H     64
#define W     64
#define S     4096        // H*W (=Ho*Wo)
#define K2    9
#define R     2304        // CIN*K2

// im2col scratch: col[b][r][s], r = c*9 + k2   (302 MB)
__device__ float g_col[(size_t)BATCH * R * S];

// ---------------------------------------------------------------------------
// Kernel 1: deformable im2col (bilinear gather)
// grid (16, 9, 8), block 256.  thread -> (b, k2, s); loops over all c.
// ---------------------------------------------------------------------------
__global__ void __launch_bounds__(256) im2col_k(const float* __restrict__ x,
                                                const float* __restrict__ off) {
    const int s  = blockIdx.x * 256 + threadIdx.x;
    const int k2 = blockIdx.y;
    const int b  = blockIdx.z;
    const int ho = s >> 6;
    const int wo = s & 63;

    const float dy = off[((size_t)b * 18 + 2 * k2)     * S + s];
    const float dx = off[((size_t)b * 18 + 2 * k2 + 1) * S + s];

    const float py = (float)(ho - 1 + k2 / 3) + dy;
    const float px = (float)(wo - 1 + k2 % 3) + dx;

    const float yf = floorf(py), xf = floorf(px);
    const int y0 = (int)yf, x0 = (int)xf;
    const float ly = py - yf, lx = px - xf;
    const float hy = 1.0f - ly, hx = 1.0f - lx;

    const bool vy0 = (y0 >= 0) && (y0 < H);
    const bool vy1 = (y0 >= -1) && (y0 < H - 1);
    const bool vx0 = (x0 >= 0) && (x0 < W);
    const bool vx1 = (x0 >= -1) && (x0 < W - 1);

    const float w00 = hy * hx * (float)(vy0 && vx0);
    const float w01 = hy * lx * (float)(vy0 && vx1);
    const float w10 = ly * hx * (float)(vy1 && vx0);
    const float w11 = ly * lx * (float)(vy1 && vx1);

    const int cy0 = min(max(y0, 0), H - 1);
    const int cy1 = min(max(y0 + 1, 0), H - 1);
    const int cx0 = min(max(x0, 0), W - 1);
    const int cx1 = min(max(x0 + 1, 0), W - 1);

    const int i00 = (cy0 << 6) + cx0;
    const int i01 = (cy0 << 6) + cx1;
    const int i10 = (cy1 << 6) + cx0;
    const int i11 = (cy1 << 6) + cx1;

    const float* xb = x + ((size_t)b << 20);                // b * CIN * S
    float* cp = g_col + (size_t)b * R * S + (size_t)k2 * S + s;

#pragma unroll 8
    for (int c = 0; c < CIN; c++) {
        const float* xp = xb + ((size_t)c << 12);           // c * S
        float v = w00 * xp[i00] + w01 * xp[i01] + w10 * xp[i10] + w11 * xp[i11];
        cp[(size_t)c * (K2 * S)] = v;                       // stride 9*4096 per c
    }
}

// ---------------------------------------------------------------------------
// Kernel 2: batched GEMM  out[b] (256x4096) = weight (256x2304) * col[b] (2304x4096)
// TF32 mma.sync m16n8k8, fp32 accumulate.
// Block tile 128x128, kTile 32, 8 warps (2M x 4N), warp tile 64x32.
// ---------------------------------------------------------------------------
#define KTILE   32
#define NKT     (R / KTILE)       // 72
#define A_LD    36                // 32 + 4 pad  (conflict-free frag loads)
#define B_LD    136               // 128 + 8 pad
#define A_BUF   (128 * A_LD)      // words per buffer
#define B_BUF   (KTILE * B_LD)
#define SMEM_WORDS (2 * A_BUF + 2 * B_BUF)
#define SMEM_BYTES (SMEM_WORDS * 4)

__device__ __forceinline__ unsigned f2tf(float f) {
    unsigned r;
    asm("cvt.rna.tf32.f32 %0, %1;" : "=r"(r) : "f"(f));
    return r;
}

__device__ __forceinline__ void mma8(float* c, const unsigned* a, const unsigned* b) {
    asm volatile(
        "mma.sync.aligned.m16n8k8.row.col.f32.tf32.tf32.f32 "
        "{%0,%1,%2,%3}, {%4,%5,%6,%7}, {%8,%9}, {%0,%1,%2,%3};\n"
        : "+f"(c[0]), "+f"(c[1]), "+f"(c[2]), "+f"(c[3])
        : "r"(a[0]), "r"(a[1]), "r"(a[2]), "r"(a[3]), "r"(b[0]), "r"(b[1]));
}

__global__ void __launch_bounds__(256) gemm_k(const float* __restrict__ Wt,
                                              float* __restrict__ out) {
    extern __shared__ unsigned sm[];
    unsigned* As = sm;                 // [2][128][A_LD]
    unsigned* Bs = sm + 2 * A_BUF;     // [2][KTILE][B_LD]

    const int b     = blockIdx.z;
    const int mBase = blockIdx.y * 128;
    const int nBase = blockIdx.x * 128;

    const int tid  = threadIdx.x;
    const int warp = tid >> 5;
    const int lane = tid & 31;
    const int wm   = (warp >> 2) * 64;   // warp M offset (0/64)
    const int wn   = (warp & 3) * 32;    // warp N offset (0/32/64/96)
    const int g    = lane >> 2;          // group id 0..7
    const int tig  = lane & 3;           // thread in group 0..3

    const float* Ag = Wt + (size_t)mBase * R;
    const float* Bg = g_col + (size_t)b * R * S + nBase;

    const int arow = tid >> 3;           // 0..31
    const int acol = (tid & 7) * 4;      // 0..28
    const int brow = tid >> 5;           // 0..7
    const int bcol = (tid & 31) * 4;     // 0..124

    float acc[4][4][4];
#pragma unroll
    for (int i = 0; i < 4; i++)
#pragma unroll
        for (int j = 0; j < 4; j++)
#pragma unroll
            for (int k = 0; k < 4; k++) acc[i][j][k] = 0.0f;

    // prologue: load k-tile 0 into buffer 0
#pragma unroll
    for (int p = 0; p < 4; p++) {
        float4 v = *(const float4*)(Ag + (size_t)(p * 32 + arow) * R + acol);
        unsigned* d = As + (p * 32 + arow) * A_LD + acol;
        d[0] = f2tf(v.x); d[1] = f2tf(v.y); d[2] = f2tf(v.z); d[3] = f2tf(v.w);
    }
#pragma unroll
    for (int p = 0; p < 4; p++) {
        float4 v = *(const float4*)(Bg + (size_t)(p * 8 + brow) * S + bcol);
        unsigned* d = Bs + (p * 8 + brow) * B_LD + bcol;
        d[0] = f2tf(v.x); d[1] = f2tf(v.y); d[2] = f2tf(v.z); d[3] = f2tf(v.w);
    }
    __syncthreads();

    int cur = 0;
    for (int kt = 0; kt < NKT; kt++) {
        float4 na[4], nb[4];
        const bool more = (kt + 1 < NKT);
        if (more) {
            const int kb = (kt + 1) * KTILE;
#pragma unroll
            for (int p = 0; p < 4; p++)
                na[p] = *(const float4*)(Ag + (size_t)(p * 32 + arow) * R + kb + acol);
#pragma unroll
            for (int p = 0; p < 4; p++)
                nb[p] = *(const float4*)(Bg + (size_t)(kb + p * 8 + brow) * S + bcol);
        }

        const unsigned* A  = As + cur * A_BUF;
        const unsigned* Bm = Bs + cur * B_BUF;

#pragma unroll
        for (int ks = 0; ks < 4; ks++) {
            const int kk = ks * 8 + tig;
            unsigned af[4][4], bf[4][2];
#pragma unroll
            for (int mt = 0; mt < 4; mt++) {
                const int mr = wm + mt * 16 + g;
                af[mt][0] = A[mr * A_LD + kk];
                af[mt][1] = A[(mr + 8) * A_LD + kk];
                af[mt][2] = A[mr * A_LD + kk + 4];
                af[mt][3] = A[(mr + 8) * A_LD + kk + 4];
            }
#pragma unroll
            for (int nt = 0; nt < 4; nt++) {
                const int nc = wn + nt * 8 + g;
                bf[nt][0] = Bm[kk * B_LD + nc];
                bf[nt][1] = Bm[(kk + 4) * B_LD + nc];
            }
#pragma unroll
            for (int mt = 0; mt < 4; mt++)
#pragma unroll
                for (int nt = 0; nt < 4; nt++)
                    mma8(acc[mt][nt], af[mt], bf[nt]);
        }

        if (more) {
            const int nxt = cur ^ 1;
            unsigned* Ad = As + nxt * A_BUF;
            unsigned* Bd = Bs + nxt * B_BUF;
#pragma unroll
            for (int p = 0; p < 4; p++) {
                unsigned* d = Ad + (p * 32 + arow) * A_LD + acol;
                d[0] = f2tf(na[p].x); d[1] = f2tf(na[p].y);
                d[2] = f2tf(na[p].z); d[3] = f2tf(na[p].w);
            }
#pragma unroll
            for (int p = 0; p < 4; p++) {
                unsigned* d = Bd + (p * 8 + brow) * B_LD + bcol;
                d[0] = f2tf(nb[p].x); d[1] = f2tf(nb[p].y);
                d[2] = f2tf(nb[p].z); d[3] = f2tf(nb[p].w);
            }
            __syncthreads();
            cur = nxt;
        }
    }

    // epilogue
    float* ob = out + ((size_t)b * COUT + mBase) * S + nBase;
#pragma unroll
    for (int mt = 0; mt < 4; mt++) {
#pragma unroll
        for (int nt = 0; nt < 4; nt++) {
            const int mr = wm + mt * 16 + g;
            const int nc = wn + nt * 8 + 2 * tig;
            *(float2*)(ob + (size_t)mr * S + nc) =
                make_float2(acc[mt][nt][0], acc[mt][nt][1]);
            *(float2*)(ob + (size_t)(mr + 8) * S + nc) =
                make_float2(acc[mt][nt][2], acc[mt][nt][3]);
        }
    }
}

// ---------------------------------------------------------------------------
extern "C" void kernel_launch(void* const* d_in, const int* in_sizes, int n_in,
                              void* d_out, int out_size) {
    const float* x   = (const float*)d_in[0];
    const float* off = (const float*)d_in[1];
    const float* wt  = (const float*)d_in[2];
    float* out       = (float*)d_out;

    im2col_k<<<dim3(S / 256, K2, BATCH), 256>>>(x, off);

    cudaFuncSetAttribute(gemm_k, cudaFuncAttributeMaxDynamicSharedMemorySize,
                         SMEM_BYTES);
    gemm_k<<<dim3(S / 128, COUT / 128, BATCH), 256, SMEM_BYTES>>>(wt, out);
}

// round 6
// speedup vs baseline: 1.0200x; 1.0200x over previous
#include <cuda_runtime.h>

// Problem constants
#define BATCH 8
#define CIN   256
#define COUT  256
#define H     64
#define W     64
#define S     4096        // H*W (=Ho*Wo)
#define K2    9
#define R     2304        // CIN*K2

// Scratch: col[b][r][s] (tf32-rounded), r = c*9 + k2  (302 MB)
__device__ float g_col[(size_t)BATCH * R * S];
// Scratch: tf32-rounded weights, [COUT][R]
__device__ float g_wt[(size_t)COUT * R];

__device__ __forceinline__ unsigned f2tf(float f) {
    unsigned r;
    asm("cvt.rna.tf32.f32 %0, %1;" : "=r"(r) : "f"(f));
    return r;
}

// ---------------------------------------------------------------------------
// Kernel 0: pre-round weights to tf32 bit patterns
// ---------------------------------------------------------------------------
__global__ void __launch_bounds__(1024) cvtw_k(const float* __restrict__ w) {
    const int i = blockIdx.x * 1024 + threadIdx.x;   // COUT*R = 576*1024 exactly
    g_wt[i] = __uint_as_float(f2tf(w[i]));
}

// ---------------------------------------------------------------------------
// Kernel 1: deformable im2col (bilinear gather), stores tf32-rounded values
// ---------------------------------------------------------------------------
__global__ void __launch_bounds__(256) im2col_k(const float* __restrict__ x,
                                                const float* __restrict__ off) {
    const int s  = blockIdx.x * 256 + threadIdx.x;
    const int k2 = blockIdx.y;
    const int b  = blockIdx.z;
    const int ho = s >> 6;
    const int wo = s & 63;

    const float dy = off[((size_t)b * 18 + 2 * k2)     * S + s];
    const float dx = off[((size_t)b * 18 + 2 * k2 + 1) * S + s];

    const float py = (float)(ho - 1 + k2 / 3) + dy;
    const float px = (float)(wo - 1 + k2 % 3) + dx;

    const float yf = floorf(py), xf = floorf(px);
    const int y0 = (int)yf, x0 = (int)xf;
    const float ly = py - yf, lx = px - xf;
    const float hy = 1.0f - ly, hx = 1.0f - lx;

    const bool vy0 = (y0 >= 0) && (y0 < H);
    const bool vy1 = (y0 >= -1) && (y0 < H - 1);
    const bool vx0 = (x0 >= 0) && (x0 < W);
    const bool vx1 = (x0 >= -1) && (x0 < W - 1);

    const float w00 = hy * hx * (float)(vy0 && vx0);
    const float w01 = hy * lx * (float)(vy0 && vx1);
    const float w10 = ly * hx * (float)(vy1 && vx0);
    const float w11 = ly * lx * (float)(vy1 && vx1);

    const int cy0 = min(max(y0, 0), H - 1);
    const int cy1 = min(max(y0 + 1, 0), H - 1);
    const int cx0 = min(max(x0, 0), W - 1);
    const int cx1 = min(max(x0 + 1, 0), W - 1);

    const int i00 = (cy0 << 6) + cx0;
    const int i01 = (cy0 << 6) + cx1;
    const int i10 = (cy1 << 6) + cx0;
    const int i11 = (cy1 << 6) + cx1;

    const float* xb = x + ((size_t)b << 20);                // b * CIN * S
    float* cp = g_col + (size_t)b * R * S + (size_t)k2 * S + s;

#pragma unroll 8
    for (int c = 0; c < CIN; c++) {
        const float* xp = xb + ((size_t)c << 12);           // c * S
        float v = w00 * xp[i00] + w01 * xp[i01] + w10 * xp[i10] + w11 * xp[i11];
        cp[(size_t)c * (K2 * S)] = __uint_as_float(f2tf(v));
    }
}

// ---------------------------------------------------------------------------
// Kernel 2: batched GEMM  out[b] (256x4096) = g_wt (256x2304) * col[b] (2304x4096)
// TF32 mma.sync m16n8k8, fp32 accumulate, cp.async 3-stage pipeline.
// Block tile 128x128, kTile 32, 8 warps (2M x 4N), warp tile 64x32.
// ---------------------------------------------------------------------------
#define KTILE   32
#define NKT     (R / KTILE)       // 72
#define A_LD    36                // 32 + 4 pad  (conflict-free frag loads)
#define B_LD    136               // 128 + 8 pad
#define A_BUF   (128 * A_LD)      // 4608 words
#define B_BUF   (KTILE * B_LD)    // 4352 words
#define STAGES  3
#define STAGE_WORDS (A_BUF + B_BUF)
#define SMEM_BYTES  (STAGES * STAGE_WORDS * 4)   // 107,520 B

#define CP_ASYNC16(dst, src) \
    asm volatile("cp.async.cg.shared.global [%0], [%1], 16;\n" :: "r"(dst), "l"(src))
#define CP_COMMIT() asm volatile("cp.async.commit_group;\n")
#define CP_WAIT(n)  asm volatile("cp.async.wait_group %0;\n" :: "n"(n))

__device__ __forceinline__ void mma8(float* c, const unsigned* a, const unsigned* b) {
    asm volatile(
        "mma.sync.aligned.m16n8k8.row.col.f32.tf32.tf32.f32 "
        "{%0,%1,%2,%3}, {%4,%5,%6,%7}, {%8,%9}, {%0,%1,%2,%3};\n"
        : "+f"(c[0]), "+f"(c[1]), "+f"(c[2]), "+f"(c[3])
        : "r"(a[0]), "r"(a[1]), "r"(a[2]), "r"(a[3]), "r"(b[0]), "r"(b[1]));
}

__global__ void __launch_bounds__(256) gemm_k(float* __restrict__ out) {
    extern __shared__ unsigned sm[];

    const int b     = blockIdx.z;
    const int mBase = blockIdx.y * 128;
    const int nBase = blockIdx.x * 128;

    const int tid  = threadIdx.x;
    const int warp = tid >> 5;
    const int lane = tid & 31;
    const int wm   = (warp >> 2) * 64;   // warp M offset (0/64)
    const int wn   = (warp & 3) * 32;    // warp N offset (0/32/64/96)
    const int g    = lane >> 2;          // group id 0..7
    const int tig  = lane & 3;           // thread in group 0..3

    const float* Ag = g_wt + (size_t)mBase * R;
    const float* Bg = g_col + (size_t)b * R * S + nBase;

    const int arow = tid >> 3;           // 0..31
    const int acol = (tid & 7) * 4;      // 0..28
    const int brow = tid >> 5;           // 0..7
    const int bcol = (tid & 31) * 4;     // 0..124

    const unsigned smem_base = (unsigned)__cvta_generic_to_shared(sm);

    float acc[4][4][4];
#pragma unroll
    for (int i = 0; i < 4; i++)
#pragma unroll
        for (int j = 0; j < 4; j++)
#pragma unroll
            for (int k = 0; k < 4; k++) acc[i][j][k] = 0.0f;

    // ---- async load of one k-tile into a pipeline stage ----
    auto load_stage = [&](int stage, int kt) {
        const int kb = kt * KTILE;
        const unsigned sa = smem_base + stage * (STAGE_WORDS * 4);
        const unsigned sb = sa + A_BUF * 4;
#pragma unroll
        for (int p = 0; p < 4; p++)
            CP_ASYNC16(sa + (((p * 32 + arow) * A_LD + acol) << 2),
                       Ag + (size_t)(p * 32 + arow) * R + kb + acol);
#pragma unroll
        for (int p = 0; p < 4; p++)
            CP_ASYNC16(sb + (((p * 8 + brow) * B_LD + bcol) << 2),
                       Bg + (size_t)(kb + p * 8 + brow) * S + bcol);
    };

    // prologue: fill STAGES-1 stages
#pragma unroll
    for (int st = 0; st < STAGES - 1; st++) {
        load_stage(st, st);
        CP_COMMIT();
    }
    CP_WAIT(STAGES - 2);
    __syncthreads();

    int cur = 0;
    for (int kt = 0; kt < NKT; kt++) {
        // prefetch k-tile kt+STAGES-1 into the stage we finished STAGES-1 iters ago
        const int pf = kt + STAGES - 1;
        if (pf < NKT) {
            int pst = cur + (STAGES - 1);
            if (pst >= STAGES) pst -= STAGES;
            load_stage(pst, pf);
        }
        CP_COMMIT();

        const unsigned* A  = sm + cur * STAGE_WORDS;
        const unsigned* Bm = A + A_BUF;

#pragma unroll
        for (int ks = 0; ks < 4; ks++) {
            const int kk = ks * 8 + tig;
            unsigned af[4][4], bf[4][2];
#pragma unroll
            for (int mt = 0; mt < 4; mt++) {
                const int mr = wm + mt * 16 + g;
                af[mt][0] = A[mr * A_LD + kk];
                af[mt][1] = A[(mr + 8) * A_LD + kk];
                af[mt][2] = A[mr * A_LD + kk + 4];
                af[mt][3] = A[(mr + 8) * A_LD + kk + 4];
            }
#pragma unroll
            for (int nt = 0; nt < 4; nt++) {
                const int nc = wn + nt * 8 + g;
                bf[nt][0] = Bm[kk * B_LD + nc];
                bf[nt][1] = Bm[(kk + 4) * B_LD + nc];
            }
#pragma unroll
            for (int mt = 0; mt < 4; mt++)
#pragma unroll
                for (int nt = 0; nt < 4; nt++)
                    mma8(acc[mt][nt], af[mt], bf[nt]);
        }

        CP_WAIT(STAGES - 2);
        __syncthreads();
        cur = (cur + 1 == STAGES) ? 0 : cur + 1;
    }

    // epilogue
    float* ob = out + ((size_t)b * COUT + mBase) * S + nBase;
#pragma unroll
    for (int mt = 0; mt < 4; mt++) {
#pragma unroll
        for (int nt = 0; nt < 4; nt++) {
            const int mr = wm + mt * 16 + g;
            const int nc = wn + nt * 8 + 2 * tig;
            *(float2*)(ob + (size_t)mr * S + nc) =
                make_float2(acc[mt][nt][0], acc[mt][nt][1]);
            *(float2*)(ob + (size_t)(mr + 8) * S + nc) =
                make_float2(acc[mt][nt][2], acc[mt][nt][3]);
        }
    }
}

// ---------------------------------------------------------------------------
extern "C" void kernel_launch(void* const* d_in, const int* in_sizes, int n_in,
                              void* d_out, int out_size) {
    const float* x   = (const float*)d_in[0];
    const float* off = (const float*)d_in[1];
    const float* wt  = (const float*)d_in[2];
    float* out       = (float*)d_out;

    cvtw_k<<<(COUT * R) / 1024, 1024>>>(wt);
    im2col_k<<<dim3(S / 256, K2, BATCH), 256>>>(x, off);

    cudaFuncSetAttribute(gemm_k, cudaFuncAttributeMaxDynamicSharedMemorySize,
                         SMEM_BYTES);
    gemm_k<<<dim3(S / 128, COUT / 128, BATCH), 256, SMEM_BYTES>>>(out);
}